// round 10
// baseline (speedup 1.0000x reference)
#include <cuda_runtime.h>
#include <cuda_fp16.h>
#include <mma.h>
#include <cstdint>
using namespace nvcuda;

#define SCALE_F 0.17677669529663687f   // 32^-0.5

// device scratch
__device__ __half g_w1[8 * 96 * 256];        // per-head fused [q(scaled)|k|v][256]
__device__ __half g_w4[256 * 256];           // wp as half [n][k]
__device__ float  g_bf[8 * 64 * 64];         // btab[rel_idx] per head
__device__ float  g_b1v[8 * 96];             // fused bias (q part scaled)
__device__ __half g_O[(size_t)8192 * 64 * 256];  // attention output, half

// ---- kernel A smem (pitches in elements) ----
#define XP   264   // X [64][264] half
#define QKP  104   // qkv head [64][104] half
#define SPP  68    // fp32 scratch [64][68]
#define PHP  72    // P overlay half pitch
#define WSP  40    // GEMM1 weight chunk [96][40] half x2 (overlaid on sp)
#define SM_X   0u
#define SM_QK  33792u
#define SM_SP  47104u            // 17408 bytes: sp / ph / ws0+ws1 overlay
#define SMEM_A 64512u

// ---- kernel B smem ----
#define OAP  264   // O tile [64][264] half
#define WBP  40    // wp chunk [256][40] half x2
#define BFP  264   // bias tile [16][264] f32
#define SMB_OA 0u
#define SMB_WS 33792u            // 2 x 20480
#define SMB_BF 74752u            // 16896
#define SMEM_B 91648u

typedef wmma::fragment<wmma::matrix_a, 16, 16, 16, __half, wmma::row_major> FragA;
typedef wmma::fragment<wmma::matrix_b, 16, 16, 16, __half, wmma::col_major> FragBc;
typedef wmma::fragment<wmma::matrix_b, 16, 16, 16, __half, wmma::row_major> FragBr;
typedef wmma::fragment<wmma::accumulator, 16, 16, 16, float> FragC;

__device__ __forceinline__ uint32_t smem_u32(const void* p) {
    uint32_t a;
    asm("{ .reg .u64 t; cvta.to.shared.u64 t, %1; cvt.u32.u64 %0, t; }" : "=r"(a) : "l"(p));
    return a;
}
__device__ __forceinline__ void cp16(uint32_t dst, const void* src) {
    asm volatile("cp.async.ca.shared.global [%0], [%1], 16;" :: "r"(dst), "l"(src));
}
#define CP_COMMIT() asm volatile("cp.async.commit_group;" ::: "memory")
#define CP_WAIT0()  asm volatile("cp.async.wait_group 0;" ::: "memory")

// ---------------- prep: pack weights fp16 / pre-gather bias ----------------
__global__ void prep_kernel(const float* __restrict__ wq,  const float* __restrict__ bq,
                            const float* __restrict__ wkv, const float* __restrict__ bkv,
                            const float* __restrict__ wp,
                            const float* __restrict__ btab, const int* __restrict__ ridx)
{
    int idx = blockIdx.x * 256 + threadIdx.x;
    if (idx < 196608) {                       // g_w1
        int h = idx / 24576, r = idx % 24576;
        int f = r >> 8, c = r & 255;
        float v;
        if (f < 32)      v = wq[(size_t)(h * 32 + f) * 256 + c] * SCALE_F;
        else if (f < 64) v = wkv[(size_t)(h * 32 + f - 32) * 256 + c];
        else             v = wkv[(size_t)(256 + h * 32 + f - 64) * 256 + c];
        g_w1[idx] = __float2half_rn(v);
    } else if (idx < 262144) {                // g_w4
        int i = idx - 196608;
        g_w4[i] = __float2half_rn(wp[i]);
    } else if (idx < 294912) {                // g_bf
        int i = idx - 262144;
        int h = i >> 12, nm = i & 4095;
        g_bf[i] = btab[ridx[nm] * 8 + h];
    } else if (idx < 295680) {                // g_b1v
        int i = idx - 294912;
        int h = i / 96, f = i % 96;
        float v;
        if (f < 32)      v = bq[h * 32 + f] * SCALE_F;
        else if (f < 64) v = bkv[h * 32 + f - 32];
        else             v = bkv[256 + h * 32 + f - 64];
        g_b1v[i] = v;
    }
}

// ---------------- kernel A: QKV + attention -> g_O ----------------
__global__ __launch_bounds__(256, 3)
void attn_kernel(const float* __restrict__ x, const float* __restrict__ mask)
{
    extern __shared__ char smem[];
    __half* xs  = (__half*)(smem + SM_X);
    __half* qk  = (__half*)(smem + SM_QK);
    float*  sp  = (float*)(smem + SM_SP);
    __half* ph  = (__half*)(smem + SM_SP);   // P overlay, pitch 72
    __half* ws0 = (__half*)(smem + SM_SP);   // GEMM1 weight dbuf overlay
    __half* ws1 = ws0 + 96 * WSP;

    const uint32_t wsa0 = smem_u32(ws0);
    const uint32_t wsa1 = smem_u32(ws1);
    const int tid = threadIdx.x;
    const int w   = tid >> 5;
    const int b   = blockIdx.x;

    // stage X as fp16
    const float4* xg = (const float4*)(x + (size_t)b * 16384);
    #pragma unroll
    for (int i = 0; i < 16; i++) {
        int idx = tid + 256 * i;
        int t = idx >> 6, c4 = idx & 63;
        float4 v = xg[idx];
        __half2* d = (__half2*)(xs + t * XP + c4 * 4);
        d[0] = __floats2half2_rn(v.x, v.y);
        d[1] = __floats2half2_rn(v.z, v.w);
    }
    __syncthreads();

    const int mi = w >> 1;   // row tile
    const int nh = w & 1;    // col half

    for (int h = 0; h < 8; h++) {
        const __half* w1h = g_w1 + h * 24576;
        // ---- GEMM1: QKV_h[64,96] = X @ W1_h^T ; 8 K32 chunks, dbuf ----
        FragC acc[3];
        #pragma unroll
        for (int j = 0; j < 3; j++) wmma::fill_fragment(acc[j], 0.f);

        {   // prologue chunk 0 -> ws0 : 96 rows x 4 x16B = 6144 B
            #pragma unroll
            for (int i = 0; i < 2; i++) {
                int idx = tid + 256 * i;
                if (idx < 384) {
                    int f = idx >> 2, p = idx & 3;
                    cp16(wsa0 + f * 80 + p * 16, w1h + f * 256 + p * 8);
                }
            }
            CP_COMMIT();
        }
        for (int kc = 0; kc < 8; kc++) {
            CP_WAIT0();
            __syncthreads();
            if (kc < 7) {
                uint32_t dst = (kc & 1) ? wsa0 : wsa1;
                #pragma unroll
                for (int i = 0; i < 2; i++) {
                    int idx = tid + 256 * i;
                    if (idx < 384) {
                        int f = idx >> 2, p = idx & 3;
                        cp16(dst + f * 80 + p * 16, w1h + f * 256 + (kc + 1) * 32 + p * 8);
                    }
                }
                CP_COMMIT();
            }
            __half* wb = (kc & 1) ? ws1 : ws0;
            #pragma unroll
            for (int k8 = 0; k8 < 2; k8++) {
                FragA fa;
                wmma::load_matrix_sync(fa, xs + mi * 16 * XP + kc * 32 + k8 * 16, XP);
                #pragma unroll
                for (int j = 0; j < 3; j++) {
                    FragBc fb;
                    wmma::load_matrix_sync(fb, wb + (nh * 3 + j) * 16 * WSP + k8 * 16, WSP);
                    wmma::mma_sync(acc[j], fa, fb, acc[j]);
                }
            }
        }
        __syncthreads();   // last mma done before sp overlay writes

        // ---- bias fixup -> qk half (2 batches of 48 cols) ----
        #pragma unroll
        for (int bb = 0; bb < 2; bb++) {
            if (nh == bb) {
                #pragma unroll
                for (int j = 0; j < 3; j++)
                    wmma::store_matrix_sync(sp + mi * 16 * SPP + j * 16, acc[j], SPP, wmma::mem_row_major);
            }
            __syncthreads();
            #pragma unroll
            for (int i = 0; i < 12; i++) {
                int idx = tid + 256 * i;
                int t = idx / 48, c = idx % 48;
                int col = bb * 48 + c;
                qk[t * QKP + col] = __float2half_rn(sp[t * SPP + c] + g_b1v[h * 96 + col]);
            }
            __syncthreads();
        }

        // ---- GEMM2: S = Q K^T -> sp ----
        {
            FragC c2[2];
            #pragma unroll
            for (int j = 0; j < 2; j++) wmma::fill_fragment(c2[j], 0.f);
            #pragma unroll
            for (int k8 = 0; k8 < 2; k8++) {
                FragA fa;
                wmma::load_matrix_sync(fa, qk + mi * 16 * QKP + k8 * 16, QKP);
                #pragma unroll
                for (int j = 0; j < 2; j++) {
                    FragBc fb;
                    wmma::load_matrix_sync(fb, qk + (nh * 2 + j) * 16 * QKP + 32 + k8 * 16, QKP);
                    wmma::mma_sync(c2[j], fa, fb, c2[j]);
                }
            }
            #pragma unroll
            for (int j = 0; j < 2; j++)
                wmma::store_matrix_sync(sp + mi * 16 * SPP + (nh * 2 + j) * 16, c2[j], SPP, wmma::mem_row_major);
        }
        __syncthreads();

        // ---- softmax: 4 threads/row -> ph (half, pitch 72) ----
        {
            int n = tid >> 2, q = tid & 3;
            const float* srow = sp + n * SPP + q * 16;
            const float* brow = g_bf + (h * 64 + n) * 64 + q * 16;
            const float* mrow = mask + (size_t)(b & 4095) * 4096 + n * 64 + q * 16;
            float vb[16];
            float mx = -1e30f;
            #pragma unroll
            for (int m = 0; m < 16; m++) {
                float v = srow[m] + brow[m] + __ldg(mrow + m);
                vb[m] = v;
                mx = fmaxf(mx, v);
            }
            mx = fmaxf(mx, __shfl_xor_sync(0xffffffffu, mx, 1));
            mx = fmaxf(mx, __shfl_xor_sync(0xffffffffu, mx, 2));
            float s = 0.f;
            #pragma unroll
            for (int m = 0; m < 16; m++) {
                float p = __expf(vb[m] - mx);
                vb[m] = p;
                s += p;
            }
            s += __shfl_xor_sync(0xffffffffu, s, 1);
            s += __shfl_xor_sync(0xffffffffu, s, 2);
            float inv = 1.f / s;
            __syncthreads();               // sp reads done before ph overlay write
            #pragma unroll
            for (int m = 0; m < 16; m++)
                ph[n * PHP + q * 16 + m] = __float2half_rn(vb[m] * inv);
        }
        __syncthreads();

        // ---- GEMM3: O_h = P @ V -> sp -> g_O (half) ----
        {
            int m3 = w >> 1, n3 = w & 1;
            FragC c3; wmma::fill_fragment(c3, 0.f);
            #pragma unroll
            for (int k8 = 0; k8 < 4; k8++) {
                FragA fa; FragBr fb;
                wmma::load_matrix_sync(fa, ph + m3 * 16 * PHP + k8 * 16, PHP);
                wmma::load_matrix_sync(fb, qk + (k8 * 16) * QKP + 64 + n3 * 16, QKP);
                wmma::mma_sync(c3, fa, fb, c3);
            }
            __syncthreads();               // ph reads done before sp frag stores
            wmma::store_matrix_sync(sp + m3 * 16 * SPP + n3 * 16, c3, SPP, wmma::mem_row_major);
        }
        __syncthreads();
        #pragma unroll
        for (int i = 0; i < 8; i++) {
            int idx = tid + 256 * i;
            int t = idx >> 5, c = idx & 31;
            g_O[((size_t)b * 64 + t) * 256 + h * 32 + c] = __float2half_rn(sp[t * SPP + c]);
        }
        __syncthreads();   // sp free before next head's ws overlay
    }
}

// ---------------- kernel B: out = O @ wp^T + bp ----------------
__global__ __launch_bounds__(256, 2)
void outproj_kernel(const float* __restrict__ bp, float* __restrict__ out)
{
    extern __shared__ char smem[];
    __half* oa  = (__half*)(smem + SMB_OA);
    __half* wb0 = (__half*)(smem + SMB_WS);
    __half* wb1 = wb0 + 256 * WBP;
    float*  bf  = (float*)(smem + SMB_BF);

    const uint32_t oaa  = smem_u32(oa);
    const uint32_t wba0 = smem_u32(wb0);
    const uint32_t wba1 = smem_u32(wb1);
    const int tid = threadIdx.x;
    const int w   = tid >> 5;
    const int mi  = w >> 1;
    const int nh  = w & 1;
    const size_t r0 = (size_t)blockIdx.x * 64;

    // stage O tile [64][256] half (cp.async), bias tile [16][264] f32 (plain)
    const __half* og = g_O + r0 * 256;
    #pragma unroll
    for (int i = 0; i < 8; i++) {
        int idx = tid + 256 * i;
        int t = idx >> 5, p = idx & 31;
        cp16(oaa + t * 528 + p * 16, og + t * 256 + p * 8);
    }
    {   // wp chunk 0: 256 n-rows x 4 x16B = 16384 B
        int n = tid;
        #pragma unroll
        for (int p = 0; p < 4; p++)
            cp16(wba0 + n * 80 + p * 16, g_w4 + n * 256 + p * 8);
    }
    CP_COMMIT();
    #pragma unroll
    for (int i = 0; i < 16; i++) {
        int idx = tid + 256 * i;
        int rr = idx >> 8, c = idx & 255;
        bf[rr * BFP + c] = __ldg(bp + c);
    }

    FragC a[8];
    CP_WAIT0();
    __syncthreads();
    #pragma unroll
    for (int j = 0; j < 8; j++)
        wmma::load_matrix_sync(a[j], bf + nh * 128 + j * 16, BFP, wmma::mem_row_major);

    for (int kc = 0; kc < 8; kc++) {
        if (kc > 0) { CP_WAIT0(); __syncthreads(); }
        if (kc < 7) {
            uint32_t dst = (kc & 1) ? wba0 : wba1;
            int n = tid;
            #pragma unroll
            for (int p = 0; p < 4; p++)
                cp16(dst + n * 80 + p * 16, g_w4 + n * 256 + (kc + 1) * 32 + p * 8);
            CP_COMMIT();
        }
        __half* wbuf = (kc & 1) ? wb1 : wb0;
        #pragma unroll
        for (int k8 = 0; k8 < 2; k8++) {
            FragA fa;
            wmma::load_matrix_sync(fa, oa + mi * 16 * OAP + kc * 32 + k8 * 16, OAP);
            #pragma unroll
            for (int j = 0; j < 8; j++) {
                FragBc fb;
                wmma::load_matrix_sync(fb, wbuf + (nh * 8 + j) * 16 * WBP + k8 * 16, WBP);
                wmma::mma_sync(a[j], fa, fb, a[j]);
            }
        }
    }
    // direct global fragment stores (bias already in acc)
    float* og4 = out + (r0 + mi * 16) * 256 + nh * 128;
    #pragma unroll
    for (int j = 0; j < 8; j++)
        wmma::store_matrix_sync(og4 + j * 16, a[j], 256, wmma::mem_row_major);
}

extern "C" void kernel_launch(void* const* d_in, const int* in_sizes, int n_in,
                              void* d_out, int out_size)
{
    const float* x    = (const float*)d_in[0];
    const float* mask = (const float*)d_in[1];
    const float* wq   = (const float*)d_in[2];
    const float* bq   = (const float*)d_in[3];
    const float* wkv  = (const float*)d_in[4];
    const float* bkv  = (const float*)d_in[5];
    const float* wp   = (const float*)d_in[6];
    const float* bp   = (const float*)d_in[7];
    const float* bt   = (const float*)d_in[8];
    const int*   ri   = (const int*)d_in[9];
    float* out = (float*)d_out;

    prep_kernel<<<1155, 256>>>(wq, bq, wkv, bkv, wp, bt, ri);
    cudaFuncSetAttribute(attn_kernel,
                         cudaFuncAttributeMaxDynamicSharedMemorySize, SMEM_A);
    attn_kernel<<<8192, 256, SMEM_A>>>(x, mask);
    cudaFuncSetAttribute(outproj_kernel,
                         cudaFuncAttributeMaxDynamicSharedMemorySize, SMEM_B);
    outproj_kernel<<<8192, 256, SMEM_B>>>(bp, out);
}

// round 11
// speedup vs baseline: 1.2055x; 1.2055x over previous
#include <cuda_runtime.h>
#include <cuda_fp16.h>
#include <mma.h>
#include <cstdint>
using namespace nvcuda;

#define SCALE_F 0.17677669529663687f   // 32^-0.5

// prepacked weights (device scratch)
__device__ __half g_w1[8 * 96 * 256];   // per-head fused [q(scaled)|k|v][256]
__device__ __half g_w4[256 * 256];      // wp as half
__device__ float  g_bf[8 * 64 * 64];    // btab[rel_idx] per head
__device__ float  g_b1v[8 * 96];        // fused bias (q part scaled)

// smem layout (elements)
#define XP  264
#define OBP 264
#define WSP 40
#define QKP 104
#define SPP 68
#define PHP 72
#define SM_X   0u
#define SM_OB  33792u
#define SM_WS  67584u     // 2 x 96*40*2 = 15360
#define SM_QK  82944u
#define SM_SP  96256u     // 18432 B: sp fp32 / ph half overlay
#define SMEM_BYTES 114688u

typedef wmma::fragment<wmma::matrix_a, 16, 16, 16, __half, wmma::row_major> FragA;
typedef wmma::fragment<wmma::matrix_b, 16, 16, 16, __half, wmma::col_major> FragBc;
typedef wmma::fragment<wmma::matrix_b, 16, 16, 16, __half, wmma::row_major> FragBr;
typedef wmma::fragment<wmma::accumulator, 16, 16, 16, float> FragC;

__device__ __forceinline__ uint32_t smem_u32(const void* p) {
    uint32_t a;
    asm("{ .reg .u64 t; cvta.to.shared.u64 t, %1; cvt.u32.u64 %0, t; }" : "=r"(a) : "l"(p));
    return a;
}
__device__ __forceinline__ void cp16(uint32_t dst, const void* src) {
    asm volatile("cp.async.ca.shared.global [%0], [%1], 16;" :: "r"(dst), "l"(src));
}
#define CP_COMMIT() asm volatile("cp.async.commit_group;" ::: "memory")
#define CP_WAIT0()  asm volatile("cp.async.wait_group 0;" ::: "memory")

// ---------------- prep: pack weights fp16 / pre-gather bias ----------------
__global__ void prep_kernel(const float* __restrict__ wq,  const float* __restrict__ bq,
                            const float* __restrict__ wkv, const float* __restrict__ bkv,
                            const float* __restrict__ wp,
                            const float* __restrict__ btab, const int* __restrict__ ridx)
{
    int idx = blockIdx.x * 256 + threadIdx.x;
    if (idx < 196608) {                       // g_w1
        int h = idx / 24576, r = idx % 24576;
        int f = r >> 8, c = r & 255;
        float v;
        if (f < 32)      v = wq[(size_t)(h * 32 + f) * 256 + c] * SCALE_F;
        else if (f < 64) v = wkv[(size_t)(h * 32 + f - 32) * 256 + c];
        else             v = wkv[(size_t)(256 + h * 32 + f - 64) * 256 + c];
        g_w1[idx] = __float2half_rn(v);
    } else if (idx < 262144) {                // g_w4
        int i = idx - 196608;
        g_w4[i] = __float2half_rn(wp[i]);
    } else if (idx < 294912) {                // g_bf
        int i = idx - 262144;
        int h = i >> 12, nm = i & 4095;
        g_bf[i] = btab[ridx[nm] * 8 + h];
    } else if (idx < 295680) {                // g_b1v
        int i = idx - 294912;
        int h = i / 96, f = i % 96;
        float v;
        if (f < 32)      v = bq[h * 32 + f] * SCALE_F;
        else if (f < 64) v = bkv[h * 32 + f - 32];
        else             v = bkv[256 + h * 32 + f - 64];
        g_b1v[i] = v;
    }
}

// stage helpers: K=32 chunk, 16B per (row, part)
__device__ __forceinline__ void stage96(uint32_t dst, const __half* src, int tid) {
    #pragma unroll
    for (int i = 0; i < 2; i++) {
        int idx = tid + 256 * i;
        if (idx < 384) {
            int f = idx >> 2, p = idx & 3;
            cp16(dst + f * 80 + p * 16, src + f * 256 + p * 8);
        }
    }
}
__device__ __forceinline__ void stage64(uint32_t dst, const __half* src, int tid) {
    int f = tid >> 2, p = tid & 3;
    cp16(dst + f * 80 + p * 16, src + f * 256 + p * 8);
}

// ---------------- main kernel ----------------
__global__ __launch_bounds__(256, 2)
void winattn_h16d(const float* __restrict__ x, const float* __restrict__ mask,
                  const float* __restrict__ bp, float* __restrict__ out)
{
    extern __shared__ char smem[];
    __half* xs  = (__half*)(smem + SM_X);
    __half* ob  = (__half*)(smem + SM_OB);
    __half* ws0 = (__half*)(smem + SM_WS);
    __half* ws1 = ws0 + 96 * WSP;
    __half* qk  = (__half*)(smem + SM_QK);
    float*  sp  = (float*)(smem + SM_SP);
    __half* ph  = (__half*)(smem + SM_SP);   // P overlay, pitch 72 (sync-protected)

    const uint32_t wsa0 = smem_u32(ws0);
    const uint32_t wsa1 = smem_u32(ws1);
    const int tid  = threadIdx.x;
    const int w    = tid >> 5;
    const int lane = tid & 31;
    const int grp  = lane >> 2;      // acc frag row group
    const int tig  = lane & 3;       // acc frag col pair
    const int b    = blockIdx.x;

    // stage X as fp16
    const float4* xg = (const float4*)(x + (size_t)b * 16384);
    #pragma unroll
    for (int i = 0; i < 16; i++) {
        int idx = tid + 256 * i;
        int t = idx >> 6, c4 = idx & 63;
        float4 v = xg[idx];
        __half2* d = (__half2*)(xs + t * XP + c4 * 4);
        d[0] = __floats2half2_rn(v.x, v.y);
        d[1] = __floats2half2_rn(v.z, v.w);
    }

    const int mi = w >> 1;   // row tile
    const int nh = w & 1;    // col half

    // prologue: head 0 chunk 0
    stage96(wsa0, g_w1, tid);
    CP_COMMIT();

    for (int h = 0; h < 8; h++) {
        const __half* w1h = g_w1 + h * 24576;
        // ---- GEMM1: QKV_h[64,96] = X @ W1_h^T ; 8 K32 chunks, dbuf + x-phase prefetch ----
        FragC acc[3];
        #pragma unroll
        for (int j = 0; j < 3; j++) wmma::fill_fragment(acc[j], 0.f);

        for (int kc = 0; kc < 8; kc++) {
            CP_WAIT0();
            __syncthreads();
            if (kc < 7) {
                stage96((kc & 1) ? wsa0 : wsa1, w1h + (kc + 1) * 32, tid);
            } else if (h < 7) {
                stage96(wsa0, g_w1 + (h + 1) * 24576, tid);   // next head chunk0
            } else {
                stage64(wsa0, g_w4, tid);                     // GEMM4 oc0 chunk0
            }
            CP_COMMIT();
            __half* wb = (kc & 1) ? ws1 : ws0;
            #pragma unroll
            for (int k8 = 0; k8 < 2; k8++) {
                FragA fa;
                wmma::load_matrix_sync(fa, xs + mi * 16 * XP + kc * 32 + k8 * 16, XP);
                #pragma unroll
                for (int j = 0; j < 3; j++) {
                    FragBc fb;
                    wmma::load_matrix_sync(fb, wb + (nh * 3 + j) * 16 * WSP + k8 * 16, WSP);
                    wmma::mma_sync(acc[j], fa, fb, acc[j]);
                }
            }
        }

        // ---- register-direct fixup: acc (+bias) -> qk half2 ----
        #pragma unroll
        for (int j = 0; j < 3; j++) {
            int colb = (nh * 3 + j) * 16;
            #pragma unroll
            for (int p = 0; p < 4; p++) {
                int row = mi * 16 + grp + 8 * (p & 1);
                int col = colb + 8 * (p >> 1) + 2 * tig;
                float b0 = g_b1v[h * 96 + col];
                float b1 = g_b1v[h * 96 + col + 1];
                *(__half2*)(qk + row * QKP + col) =
                    __floats2half2_rn(acc[j].x[2 * p] + b0, acc[j].x[2 * p + 1] + b1);
            }
        }
        __syncthreads();

        // ---- GEMM2: S = Q K^T -> sp ----
        {
            FragC c2[2];
            #pragma unroll
            for (int j = 0; j < 2; j++) wmma::fill_fragment(c2[j], 0.f);
            #pragma unroll
            for (int k8 = 0; k8 < 2; k8++) {
                FragA fa;
                wmma::load_matrix_sync(fa, qk + mi * 16 * QKP + k8 * 16, QKP);
                #pragma unroll
                for (int j = 0; j < 2; j++) {
                    FragBc fb;
                    wmma::load_matrix_sync(fb, qk + (nh * 2 + j) * 16 * QKP + 32 + k8 * 16, QKP);
                    wmma::mma_sync(c2[j], fa, fb, c2[j]);
                }
            }
            #pragma unroll
            for (int j = 0; j < 2; j++)
                wmma::store_matrix_sync(sp + mi * 16 * SPP + (nh * 2 + j) * 16, c2[j], SPP, wmma::mem_row_major);
        }
        __syncthreads();

        // ---- softmax: 4 threads/row -> ph (half, pitch 72) ----
        {
            int n = tid >> 2, q = tid & 3;
            const float* srow = sp + n * SPP + q * 16;
            const float* brow = g_bf + (h * 64 + n) * 64 + q * 16;
            const float* mrow = mask + (size_t)(b & 4095) * 4096 + n * 64 + q * 16;
            float vb[16];
            float mx = -1e30f;
            #pragma unroll
            for (int m = 0; m < 16; m++) {
                float v = srow[m] + brow[m] + __ldg(mrow + m);
                vb[m] = v;
                mx = fmaxf(mx, v);
            }
            mx = fmaxf(mx, __shfl_xor_sync(0xffffffffu, mx, 1));
            mx = fmaxf(mx, __shfl_xor_sync(0xffffffffu, mx, 2));
            float s = 0.f;
            #pragma unroll
            for (int m = 0; m < 16; m++) {
                float p = __expf(vb[m] - mx);
                vb[m] = p;
                s += p;
            }
            s += __shfl_xor_sync(0xffffffffu, s, 1);
            s += __shfl_xor_sync(0xffffffffu, s, 2);
            float inv = 1.f / s;
            __syncthreads();               // sp reads done before ph overlay write
            #pragma unroll
            for (int m = 0; m < 16; m++)
                ph[n * PHP + q * 16 + m] = __float2half_rn(vb[m] * inv);
        }
        __syncthreads();

        // ---- GEMM3: O_h = P @ V -> register-direct to ob half2 ----
        {
            int m3 = w >> 1, n3 = w & 1;
            FragC c3; wmma::fill_fragment(c3, 0.f);
            #pragma unroll
            for (int k8 = 0; k8 < 4; k8++) {
                FragA fa; FragBr fb;
                wmma::load_matrix_sync(fa, ph + m3 * 16 * PHP + k8 * 16, PHP);
                wmma::load_matrix_sync(fb, qk + (k8 * 16) * QKP + 64 + n3 * 16, QKP);
                wmma::mma_sync(c3, fa, fb, c3);
            }
            #pragma unroll
            for (int p = 0; p < 4; p++) {
                int row = m3 * 16 + grp + 8 * (p & 1);
                int col = h * 32 + n3 * 16 + 8 * (p >> 1) + 2 * tig;
                *(__half2*)(ob + row * OBP + col) =
                    __floats2half2_rn(c3.x[2 * p], c3.x[2 * p + 1]);
            }
        }
        // no barrier: next phase's kc-loop barriers order everything
    }
    __syncthreads();   // ob visible to all warps for GEMM4

    // ---------- GEMM4: out = Ob @ wp^T, 4 col groups of 64, prefetched ----------
    for (int oc = 0; oc < 4; oc++) {
        FragC a4[2];
        #pragma unroll
        for (int j = 0; j < 2; j++) wmma::fill_fragment(a4[j], 0.f);

        const __half* w4o = g_w4 + (size_t)oc * 64 * 256;
        for (int kc = 0; kc < 8; kc++) {
            CP_WAIT0();
            __syncthreads();
            if (kc < 7) {
                stage64((kc & 1) ? wsa0 : wsa1, w4o + (kc + 1) * 32, tid);
                CP_COMMIT();
            } else if (oc < 3) {
                stage64(wsa0, g_w4 + (size_t)(oc + 1) * 64 * 256, tid);  // next oc chunk0
                CP_COMMIT();
            }
            __half* wb = (kc & 1) ? ws1 : ws0;
            #pragma unroll
            for (int k8 = 0; k8 < 2; k8++) {
                FragA fa;
                wmma::load_matrix_sync(fa, ob + mi * 16 * OBP + kc * 32 + k8 * 16, OBP);
                #pragma unroll
                for (int j = 0; j < 2; j++) {
                    FragBc fb;
                    wmma::load_matrix_sync(fb, wb + (nh * 2 + j) * 16 * WSP + k8 * 16, WSP);
                    wmma::mma_sync(a4[j], fa, fb, a4[j]);
                }
            }
        }
        // register-direct epilogue: +bp, float2 global stores
        float* orow = out + (size_t)b * 16384;
        #pragma unroll
        for (int j = 0; j < 2; j++) {
            int colb = oc * 64 + (nh * 2 + j) * 16;
            #pragma unroll
            for (int p = 0; p < 4; p++) {
                int row = mi * 16 + grp + 8 * (p & 1);
                int col = colb + 8 * (p >> 1) + 2 * tig;
                float2 v;
                v.x = a4[j].x[2 * p]     + __ldg(bp + col);
                v.y = a4[j].x[2 * p + 1] + __ldg(bp + col + 1);
                *(float2*)(orow + row * 256 + col) = v;
            }
        }
    }
}

extern "C" void kernel_launch(void* const* d_in, const int* in_sizes, int n_in,
                              void* d_out, int out_size)
{
    const float* x    = (const float*)d_in[0];
    const float* mask = (const float*)d_in[1];
    const float* wq   = (const float*)d_in[2];
    const float* bq   = (const float*)d_in[3];
    const float* wkv  = (const float*)d_in[4];
    const float* bkv  = (const float*)d_in[5];
    const float* wp   = (const float*)d_in[6];
    const float* bp   = (const float*)d_in[7];
    const float* bt   = (const float*)d_in[8];
    const int*   ri   = (const int*)d_in[9];
    float* out = (float*)d_out;

    prep_kernel<<<1155, 256>>>(wq, bq, wkv, bkv, wp, bt, ri);
    cudaFuncSetAttribute(winattn_h16d,
                         cudaFuncAttributeMaxDynamicSharedMemorySize, SMEM_BYTES);
    winattn_h16d<<<8192, 256, SMEM_BYTES>>>(x, mask, bp, out);
}

// round 14
// speedup vs baseline: 1.5376x; 1.2755x over previous
#include <cuda_runtime.h>
#include <cuda_fp16.h>
#include <mma.h>
#include <cstdint>
using namespace nvcuda;

#define SCALE_F 0.17677669529663687f   // 32^-0.5

// prepacked weights (device scratch)
__device__ __half g_w1[8 * 96 * 256];   // per-head fused [q(scaled)|k|v][256]
__device__ __half g_w4[256 * 256];      // wp as half
__device__ float  g_bf[8 * 64 * 64];    // btab[rel_idx] per head
__device__ float  g_b1v[8 * 96];        // fused bias (q part scaled)

// smem layout (elements)
#define XP  264
#define OBP 264
#define WSP 40
#define QKP 104
#define SM_X   0u
#define SM_OB  33792u
#define SM_WS  67584u     // 2 x 96*40*2 = 15360
#define SM_QK  82944u     // 64*104*2 = 13312
#define SMEM_BYTES 96256u

typedef wmma::fragment<wmma::matrix_a, 16, 16, 16, __half, wmma::row_major> FragA;
typedef wmma::fragment<wmma::matrix_b, 16, 16, 16, __half, wmma::col_major> FragBc;
typedef wmma::fragment<wmma::accumulator, 16, 16, 16, float> FragC;

__device__ __forceinline__ uint32_t smem_u32(const void* p) {
    uint32_t a;
    asm("{ .reg .u64 t; cvta.to.shared.u64 t, %1; cvt.u32.u64 %0, t; }" : "=r"(a) : "l"(p));
    return a;
}
__device__ __forceinline__ uint32_t packh2(float lo, float hi) {
    uint32_t r;
    asm("cvt.rn.f16x2.f32 %0, %1, %2;" : "=r"(r) : "f"(hi), "f"(lo));
    return r;
}
__device__ __forceinline__ void cp16(uint32_t dst, const void* src) {
    asm volatile("cp.async.ca.shared.global [%0], [%1], 16;" :: "r"(dst), "l"(src));
}
#define CP_COMMIT() asm volatile("cp.async.commit_group;" ::: "memory")
#define CP_WAIT0()  asm volatile("cp.async.wait_group 0;" ::: "memory")

__device__ __forceinline__ void ldsm4(uint32_t a, uint32_t& r0, uint32_t& r1, uint32_t& r2, uint32_t& r3) {
    asm volatile("ldmatrix.sync.aligned.m8n8.x4.shared.b16 {%0,%1,%2,%3}, [%4];"
                 : "=r"(r0), "=r"(r1), "=r"(r2), "=r"(r3) : "r"(a));
}
__device__ __forceinline__ void ldsm4t(uint32_t a, uint32_t& r0, uint32_t& r1, uint32_t& r2, uint32_t& r3) {
    asm volatile("ldmatrix.sync.aligned.m8n8.x4.trans.shared.b16 {%0,%1,%2,%3}, [%4];"
                 : "=r"(r0), "=r"(r1), "=r"(r2), "=r"(r3) : "r"(a));
}
__device__ __forceinline__ void mma16816(float* d, const uint32_t* a, uint32_t b0, uint32_t b1) {
    asm volatile("mma.sync.aligned.m16n8k16.row.col.f32.f16.f16.f32 "
                 "{%0,%1,%2,%3}, {%4,%5,%6,%7}, {%8,%9}, {%0,%1,%2,%3};"
                 : "+f"(d[0]), "+f"(d[1]), "+f"(d[2]), "+f"(d[3])
                 : "r"(a[0]), "r"(a[1]), "r"(a[2]), "r"(a[3]), "r"(b0), "r"(b1));
}

// ---------------- prep: pack weights fp16 / pre-gather bias ----------------
__global__ void prep_kernel(const float* __restrict__ wq,  const float* __restrict__ bq,
                            const float* __restrict__ wkv, const float* __restrict__ bkv,
                            const float* __restrict__ wp,
                            const float* __restrict__ btab, const int* __restrict__ ridx)
{
    int idx = blockIdx.x * 256 + threadIdx.x;
    if (idx < 196608) {                       // g_w1
        int h = idx / 24576, r = idx % 24576;
        int f = r >> 8, c = r & 255;
        float v;
        if (f < 32)      v = wq[(size_t)(h * 32 + f) * 256 + c] * SCALE_F;
        else if (f < 64) v = wkv[(size_t)(h * 32 + f - 32) * 256 + c];
        else             v = wkv[(size_t)(256 + h * 32 + f - 64) * 256 + c];
        g_w1[idx] = __float2half_rn(v);
    } else if (idx < 262144) {                // g_w4
        int i = idx - 196608;
        g_w4[i] = __float2half_rn(wp[i]);
    } else if (idx < 294912) {                // g_bf
        int i = idx - 262144;
        int h = i >> 12, nm = i & 4095;
        g_bf[i] = btab[ridx[nm] * 8 + h];
    } else if (idx < 295680) {                // g_b1v
        int i = idx - 294912;
        int h = i / 96, f = i % 96;
        float v;
        if (f < 32)      v = bq[h * 32 + f] * SCALE_F;
        else if (f < 64) v = bkv[h * 32 + f - 32];
        else             v = bkv[256 + h * 32 + f - 64];
        g_b1v[i] = v;
    }
}

// stage helpers: K=32 chunk, 16B per (row, part)
__device__ __forceinline__ void stage96(uint32_t dst, const __half* src, int tid) {
    #pragma unroll
    for (int i = 0; i < 2; i++) {
        int idx = tid + 256 * i;
        if (idx < 384) {
            int f = idx >> 2, p = idx & 3;
            cp16(dst + f * 80 + p * 16, src + f * 256 + p * 8);
        }
    }
}
__device__ __forceinline__ void stage64(uint32_t dst, const __half* src, int tid) {
    int f = tid >> 2, p = tid & 3;
    cp16(dst + f * 80 + p * 16, src + f * 256 + p * 8);
}

// ---------------- main kernel ----------------
__global__ __launch_bounds__(256, 2)
void winattn_h16e(const float* __restrict__ x, const float* __restrict__ mask,
                  const float* __restrict__ bp, float* __restrict__ out)
{
    extern __shared__ char smem[];
    __half* xs  = (__half*)(smem + SM_X);
    __half* ob  = (__half*)(smem + SM_OB);
    __half* ws0 = (__half*)(smem + SM_WS);
    __half* ws1 = ws0 + 96 * WSP;
    __half* qk  = (__half*)(smem + SM_QK);

    const uint32_t wsa0 = smem_u32(ws0);
    const uint32_t wsa1 = smem_u32(ws1);
    const uint32_t qka  = smem_u32(qk);
    const int tid  = threadIdx.x;
    const int w    = tid >> 5;
    const int lane = tid & 31;
    const int grp  = lane >> 2;      // frag row group
    const int tig  = lane & 3;       // frag col pair
    const int li   = lane & 7;       // ldmatrix row-in-block
    const int sel  = lane >> 3;      // ldmatrix block select
    const int b    = blockIdx.x;

    // stage X as fp16
    const float4* xg = (const float4*)(x + (size_t)b * 16384);
    #pragma unroll
    for (int i = 0; i < 16; i++) {
        int idx = tid + 256 * i;
        int t = idx >> 6, c4 = idx & 63;
        float4 v = xg[idx];
        __half2* d = (__half2*)(xs + t * XP + c4 * 4);
        d[0] = __floats2half2_rn(v.x, v.y);
        d[1] = __floats2half2_rn(v.z, v.w);
    }

    const int mi = w >> 1;   // row tile (pair-duplicated in attention)
    const int nh = w & 1;    // GEMM1/4 col half; PV col half

    // ldmatrix per-lane addresses (byte offsets into qk), per operand type
    //  A (Q, row-major 16x16): r0=(r0..7,c0-7) r1=(r+8,c0-7) r2=(r0-7,c+8) r3=(r+8,c+8)
    const uint32_t addrA = qka + (((sel & 1) * 8 + li) * QKP + (sel >> 1) * 8) * 2;
    //  K as B (non-trans):     r0=(t0-7,d0-7) r1=(t0-7,d+8) r2=(t+8,d0-7) r3=(t+8,d+8)
    const uint32_t addrK = qka + (((sel >> 1) * 8 + li) * QKP + (sel & 1) * 8) * 2;
    //  V as B (trans):         r0=(t0-7,d0-7) r1=(t+8,d0-7) r2=(t0-7,d+8) r3=(t+8,d+8)
    const uint32_t addrV = qka + (((sel & 1) * 8 + li) * QKP + (sel >> 1) * 8) * 2;

    // prologue: head 0 chunk 0
    stage96(wsa0, g_w1, tid);
    CP_COMMIT();

    for (int h = 0; h < 8; h++) {
        const __half* w1h = g_w1 + h * 24576;
        // ---- GEMM1: QKV_h[64,96] = X @ W1_h^T ; 8 K32 chunks, dbuf + x-phase prefetch ----
        FragC acc[3];
        #pragma unroll
        for (int j = 0; j < 3; j++) wmma::fill_fragment(acc[j], 0.f);

        for (int kc = 0; kc < 8; kc++) {
            CP_WAIT0();
            __syncthreads();
            if (kc < 7) {
                stage96((kc & 1) ? wsa0 : wsa1, w1h + (kc + 1) * 32, tid);
            } else if (h < 7) {
                stage96(wsa0, g_w1 + (h + 1) * 24576, tid);   // next head chunk0
            } else {
                stage64(wsa0, g_w4, tid);                     // GEMM4 oc0 chunk0
            }
            CP_COMMIT();
            __half* wb = (kc & 1) ? ws1 : ws0;
            #pragma unroll
            for (int k8 = 0; k8 < 2; k8++) {
                FragA fa;
                wmma::load_matrix_sync(fa, xs + mi * 16 * XP + kc * 32 + k8 * 16, XP);
                #pragma unroll
                for (int j = 0; j < 3; j++) {
                    FragBc fb;
                    wmma::load_matrix_sync(fb, wb + (nh * 3 + j) * 16 * WSP + k8 * 16, WSP);
                    wmma::mma_sync(acc[j], fa, fb, acc[j]);
                }
            }
        }

        // ---- register-direct fixup: acc (+bias) -> qk half2 ----
        #pragma unroll
        for (int j = 0; j < 3; j++) {
            int colb = (nh * 3 + j) * 16;
            #pragma unroll
            for (int p = 0; p < 4; p++) {
                int row = mi * 16 + grp + 8 * (p & 1);
                int col = colb + 8 * (p >> 1) + 2 * tig;
                float b0 = g_b1v[h * 96 + col];
                float b1 = g_b1v[h * 96 + col + 1];
                *(uint32_t*)(qk + row * QKP + col) =
                    packh2(acc[j].x[2 * p] + b0, acc[j].x[2 * p + 1] + b1);
            }
        }
        __syncthreads();

        // ======== register-resident attention (no smem for S/P) ========
        // S[16x64] in regs: sD[c][0..1]=row grp cols 8c+2tig..; [2..3]=row grp+8
        float sD[8][4];
        #pragma unroll
        for (int c = 0; c < 8; c++)
            #pragma unroll
            for (int r = 0; r < 4; r++) sD[c][r] = 0.f;
        {
            uint32_t qa0[4], qa1[4];
            ldsm4(addrA + (mi * 16 * QKP) * 2,        qa0[0], qa0[1], qa0[2], qa0[3]);
            ldsm4(addrA + (mi * 16 * QKP + 16) * 2,   qa1[0], qa1[1], qa1[2], qa1[3]);
            #pragma unroll
            for (int tg = 0; tg < 4; tg++) {
                uint32_t k0[4], k1[4];
                ldsm4(addrK + (tg * 16 * QKP + 32) * 2, k0[0], k0[1], k0[2], k0[3]);
                ldsm4(addrK + (tg * 16 * QKP + 48) * 2, k1[0], k1[1], k1[2], k1[3]);
                mma16816(sD[2 * tg + 0], qa0, k0[0], k0[1]);
                mma16816(sD[2 * tg + 0], qa1, k1[0], k1[1]);
                mma16816(sD[2 * tg + 1], qa0, k0[2], k0[3]);
                mma16816(sD[2 * tg + 1], qa1, k1[2], k1[3]);
            }
        }
        // in-warp softmax over rows (grp, grp+8); quad shfl covers all 64 cols
        {
            int r0 = mi * 16 + grp, r1 = r0 + 8;
            const float* bfh = g_bf + h * 4096;
            const float* mkb = mask + (size_t)(b & 4095) * 4096;
            float mx0 = -1e30f, mx1 = -1e30f;
            #pragma unroll
            for (int c = 0; c < 8; c++) {
                int col = 8 * c + 2 * tig;
                float2 f0 = __ldg((const float2*)(bfh + r0 * 64 + col));
                float2 m0 = __ldg((const float2*)(mkb + r0 * 64 + col));
                float2 f1 = __ldg((const float2*)(bfh + r1 * 64 + col));
                float2 m1 = __ldg((const float2*)(mkb + r1 * 64 + col));
                sD[c][0] += f0.x + m0.x;  sD[c][1] += f0.y + m0.y;
                sD[c][2] += f1.x + m1.x;  sD[c][3] += f1.y + m1.y;
                mx0 = fmaxf(mx0, fmaxf(sD[c][0], sD[c][1]));
                mx1 = fmaxf(mx1, fmaxf(sD[c][2], sD[c][3]));
            }
            mx0 = fmaxf(mx0, __shfl_xor_sync(0xffffffffu, mx0, 1));
            mx0 = fmaxf(mx0, __shfl_xor_sync(0xffffffffu, mx0, 2));
            mx1 = fmaxf(mx1, __shfl_xor_sync(0xffffffffu, mx1, 1));
            mx1 = fmaxf(mx1, __shfl_xor_sync(0xffffffffu, mx1, 2));
            float s0 = 0.f, s1 = 0.f;
            #pragma unroll
            for (int c = 0; c < 8; c++) {
                sD[c][0] = __expf(sD[c][0] - mx0);  s0 += sD[c][0];
                sD[c][1] = __expf(sD[c][1] - mx0);  s0 += sD[c][1];
                sD[c][2] = __expf(sD[c][2] - mx1);  s1 += sD[c][2];
                sD[c][3] = __expf(sD[c][3] - mx1);  s1 += sD[c][3];
            }
            s0 += __shfl_xor_sync(0xffffffffu, s0, 1);
            s0 += __shfl_xor_sync(0xffffffffu, s0, 2);
            s1 += __shfl_xor_sync(0xffffffffu, s1, 1);
            s1 += __shfl_xor_sync(0xffffffffu, s1, 2);
            float i0 = 1.f / s0, i1 = 1.f / s1;
            #pragma unroll
            for (int c = 0; c < 8; c++) {
                sD[c][0] *= i0;  sD[c][1] *= i0;
                sD[c][2] *= i1;  sD[c][3] *= i1;
            }
        }
        // repack P into PV A-frags (D-layout == A-layout), PV over warp's 16 V cols
        {
            float oD[2][4];
            #pragma unroll
            for (int ch = 0; ch < 2; ch++)
                #pragma unroll
                for (int r = 0; r < 4; r++) oD[ch][r] = 0.f;
            #pragma unroll
            for (int kf = 0; kf < 4; kf++) {
                uint32_t pa[4];
                pa[0] = packh2(sD[2 * kf][0],     sD[2 * kf][1]);
                pa[1] = packh2(sD[2 * kf][2],     sD[2 * kf][3]);
                pa[2] = packh2(sD[2 * kf + 1][0], sD[2 * kf + 1][1]);
                pa[3] = packh2(sD[2 * kf + 1][2], sD[2 * kf + 1][3]);
                uint32_t v[4];
                ldsm4t(addrV + (kf * 16 * QKP + 64 + nh * 16) * 2, v[0], v[1], v[2], v[3]);
                mma16816(oD[0], pa, v[0], v[1]);
                mma16816(oD[1], pa, v[2], v[3]);
            }
            // register-direct O -> ob half2
            #pragma unroll
            for (int ch = 0; ch < 2; ch++) {
                int col = h * 32 + nh * 16 + 8 * ch + 2 * tig;
                int r0 = mi * 16 + grp;
                *(uint32_t*)(ob + r0 * OBP + col)       = packh2(oD[ch][0], oD[ch][1]);
                *(uint32_t*)(ob + (r0 + 8) * OBP + col) = packh2(oD[ch][2], oD[ch][3]);
            }
        }
        // no barrier: next GEMM1 kc-loop barriers order qk reuse
    }
    __syncthreads();   // ob visible to all warps for GEMM4

    // ---------- GEMM4: out = Ob @ wp^T, 4 col groups of 64, prefetched ----------
    for (int oc = 0; oc < 4; oc++) {
        FragC a4[2];
        #pragma unroll
        for (int j = 0; j < 2; j++) wmma::fill_fragment(a4[j], 0.f);

        const __half* w4o = g_w4 + (size_t)oc * 64 * 256;
        for (int kc = 0; kc < 8; kc++) {
            CP_WAIT0();
            __syncthreads();
            if (kc < 7) {
                stage64((kc & 1) ? wsa0 : wsa1, w4o + (kc + 1) * 32, tid);
                CP_COMMIT();
            } else if (oc < 3) {
                stage64(wsa0, g_w4 + (size_t)(oc + 1) * 64 * 256, tid);  // next oc chunk0
                CP_COMMIT();
            }
            __half* wb = (kc & 1) ? ws1 : ws0;
            #pragma unroll
            for (int k8 = 0; k8 < 2; k8++) {
                FragA fa;
                wmma::load_matrix_sync(fa, ob + mi * 16 * OBP + kc * 32 + k8 * 16, OBP);
                #pragma unroll
                for (int j = 0; j < 2; j++) {
                    FragBc fb;
                    wmma::load_matrix_sync(fb, wb + (nh * 2 + j) * 16 * WSP + k8 * 16, WSP);
                    wmma::mma_sync(a4[j], fa, fb, a4[j]);
                }
            }
        }
        // register-direct epilogue: +bp, float2 global stores
        float* orow = out + (size_t)b * 16384;
        #pragma unroll
        for (int j = 0; j < 2; j++) {
            int colb = oc * 64 + (nh * 2 + j) * 16;
            #pragma unroll
            for (int p = 0; p < 4; p++) {
                int row = mi * 16 + grp + 8 * (p & 1);
                int col = colb + 8 * (p >> 1) + 2 * tig;
                float2 v;
                v.x = a4[j].x[2 * p]     + __ldg(bp + col);
                v.y = a4[j].x[2 * p + 1] + __ldg(bp + col + 1);
                *(float2*)(orow + row * 256 + col) = v;
            }
        }
    }
}

extern "C" void kernel_launch(void* const* d_in, const int* in_sizes, int n_in,
                              void* d_out, int out_size)
{
    const float* x    = (const float*)d_in[0];
    const float* mask = (const float*)d_in[1];
    const float* wq   = (const float*)d_in[2];
    const float* bq   = (const float*)d_in[3];
    const float* wkv  = (const float*)d_in[4];
    const float* bkv  = (const float*)d_in[5];
    const float* wp   = (const float*)d_in[6];
    const float* bp   = (const float*)d_in[7];
    const float* bt   = (const float*)d_in[8];
    const int*   ri   = (const int*)d_in[9];
    float* out = (float*)d_out;

    prep_kernel<<<1155, 256>>>(wq, bq, wkv, bkv, wp, bt, ri);
    cudaFuncSetAttribute(winattn_h16e,
                         cudaFuncAttributeMaxDynamicSharedMemorySize, SMEM_BYTES);
    winattn_h16e<<<8192, 256, SMEM_BYTES>>>(x, mask, bp, out);
}

// round 15
// speedup vs baseline: 1.7195x; 1.1183x over previous
#include <cuda_runtime.h>
#include <cuda_fp16.h>
#include <mma.h>
#include <cstdint>
using namespace nvcuda;

#define SCALE_F 0.17677669529663687f   // 32^-0.5

// prepacked weights (device scratch)
__device__ __half g_w1[8 * 96 * 256];   // per-head fused [q(scaled)|k|v][256]
__device__ __half g_w4[256 * 256];      // wp as half
__device__ float  g_bf[8 * 64 * 64];    // btab[rel_idx] per head
__device__ float  g_b1v[8 * 96];        // fused bias (q part scaled)

// smem layout (elements / byte offsets)
#define XP  264
#define OBP 264
#define WSP 40
#define QKP 104
#define MKP 72
#define SM_X   0u         // 33792 : X [64][264] half (GEMM4: ws4 overlay)
#define SM_QK  33792u     // 13312 : qkv head [64][104] half (GEMM4: ws4B tail)
#define SM_WS  47104u     // 15360 : GEMM1 weight dbuf [96][40] x2
#define SM_OB  62464u     // 33792 : attn out [64][264] half
#define SM_MK  96256u     // 18432 : mask [64][72] f32
#define SMEM_BYTES 114688u
#define WS4A 0u           // GEMM4 weight buf A [256][40] half (20480 B)
#define WS4B 20480u       // GEMM4 weight buf B

typedef wmma::fragment<wmma::matrix_a, 16, 16, 16, __half, wmma::row_major> FragA;
typedef wmma::fragment<wmma::matrix_b, 16, 16, 16, __half, wmma::col_major> FragBc;
typedef wmma::fragment<wmma::accumulator, 16, 16, 16, float> FragC;

__device__ __forceinline__ uint32_t smem_u32(const void* p) {
    uint32_t a;
    asm("{ .reg .u64 t; cvta.to.shared.u64 t, %1; cvt.u32.u64 %0, t; }" : "=r"(a) : "l"(p));
    return a;
}
__device__ __forceinline__ uint32_t packh2(float lo, float hi) {
    uint32_t r;
    asm("cvt.rn.f16x2.f32 %0, %1, %2;" : "=r"(r) : "f"(hi), "f"(lo));
    return r;
}
__device__ __forceinline__ void cp16(uint32_t dst, const void* src) {
    asm volatile("cp.async.ca.shared.global [%0], [%1], 16;" :: "r"(dst), "l"(src));
}
#define CP_COMMIT() asm volatile("cp.async.commit_group;" ::: "memory")
#define CP_WAIT0()  asm volatile("cp.async.wait_group 0;" ::: "memory")
__device__ __forceinline__ void barg(int id) {
    asm volatile("bar.sync %0, %1;" :: "r"(id), "r"(128) : "memory");
}

__device__ __forceinline__ void ldsm4(uint32_t a, uint32_t& r0, uint32_t& r1, uint32_t& r2, uint32_t& r3) {
    asm volatile("ldmatrix.sync.aligned.m8n8.x4.shared.b16 {%0,%1,%2,%3}, [%4];"
                 : "=r"(r0), "=r"(r1), "=r"(r2), "=r"(r3) : "r"(a));
}
__device__ __forceinline__ void ldsm4t(uint32_t a, uint32_t& r0, uint32_t& r1, uint32_t& r2, uint32_t& r3) {
    asm volatile("ldmatrix.sync.aligned.m8n8.x4.trans.shared.b16 {%0,%1,%2,%3}, [%4];"
                 : "=r"(r0), "=r"(r1), "=r"(r2), "=r"(r3) : "r"(a));
}
__device__ __forceinline__ void mma16816(float* d, const uint32_t* a, uint32_t b0, uint32_t b1) {
    asm volatile("mma.sync.aligned.m16n8k16.row.col.f32.f16.f16.f32 "
                 "{%0,%1,%2,%3}, {%4,%5,%6,%7}, {%8,%9}, {%0,%1,%2,%3};"
                 : "+f"(d[0]), "+f"(d[1]), "+f"(d[2]), "+f"(d[3])
                 : "r"(a[0]), "r"(a[1]), "r"(a[2]), "r"(a[3]), "r"(b0), "r"(b1));
}

// ---------------- prep: pack weights fp16 / pre-gather bias ----------------
__global__ void prep_kernel(const float* __restrict__ wq,  const float* __restrict__ bq,
                            const float* __restrict__ wkv, const float* __restrict__ bkv,
                            const float* __restrict__ wp,
                            const float* __restrict__ btab, const int* __restrict__ ridx)
{
    int idx = blockIdx.x * 256 + threadIdx.x;
    if (idx < 196608) {                       // g_w1
        int h = idx / 24576, r = idx % 24576;
        int f = r >> 8, c = r & 255;
        float v;
        if (f < 32)      v = wq[(size_t)(h * 32 + f) * 256 + c] * SCALE_F;
        else if (f < 64) v = wkv[(size_t)(h * 32 + f - 32) * 256 + c];
        else             v = wkv[(size_t)(256 + h * 32 + f - 64) * 256 + c];
        g_w1[idx] = __float2half_rn(v);
    } else if (idx < 262144) {                // g_w4
        int i = idx - 196608;
        g_w4[i] = __float2half_rn(wp[i]);
    } else if (idx < 294912) {                // g_bf
        int i = idx - 262144;
        int h = i >> 12, nm = i & 4095;
        g_bf[i] = btab[ridx[nm] * 8 + h];
    } else if (idx < 295680) {                // g_b1v
        int i = idx - 294912;
        int h = i / 96, f = i % 96;
        float v;
        if (f < 32)      v = bq[h * 32 + f] * SCALE_F;
        else if (f < 64) v = bkv[h * 32 + f - 32];
        else             v = bkv[256 + h * 32 + f - 64];
        g_b1v[i] = v;
    }
}

// group-local staging: GEMM1 chunk, rows [nh*48, nh*48+48), 4x16B per row
__device__ __forceinline__ void stage96g(uint32_t dst, const __half* src, int gt, int nh) {
    #pragma unroll
    for (int i = 0; i < 2; i++) {
        int idx = gt + 128 * i;
        if (idx < 192) {
            int f = nh * 48 + (idx >> 2), p = idx & 3;
            cp16(dst + f * 80 + p * 16, src + f * 256 + p * 8);
        }
    }
}
// group-local staging: GEMM4 chunk, this group's 128 rows of wp
__device__ __forceinline__ void stage256g(uint32_t dst, const __half* src, int gt, int nh) {
    #pragma unroll
    for (int i = 0; i < 4; i++) {
        int idx = gt + 128 * i;
        int r128 = idx >> 2, p = idx & 3;
        int row = (r128 >> 5) * 64 + nh * 32 + (r128 & 31);
        cp16(dst + row * 80 + p * 16, src + row * 256 + p * 8);
    }
}

// ---------------- main kernel ----------------
__global__ __launch_bounds__(256, 2)
void winattn_h16f(const float* __restrict__ x, const float* __restrict__ mask,
                  const float* __restrict__ bp, float* __restrict__ out)
{
    extern __shared__ char smem[];
    __half* xs  = (__half*)(smem + SM_X);
    __half* ob  = (__half*)(smem + SM_OB);
    __half* ws0 = (__half*)(smem + SM_WS);
    __half* ws1 = ws0 + 96 * WSP;
    __half* qk  = (__half*)(smem + SM_QK);
    float*  mks = (float*)(smem + SM_MK);
    __half* w4a = (__half*)(smem + WS4A);
    __half* w4b = (__half*)(smem + WS4B);

    const uint32_t wsa0 = smem_u32(ws0);
    const uint32_t wsa1 = smem_u32(ws1);
    const uint32_t w4aa = smem_u32(w4a);
    const uint32_t w4ba = smem_u32(w4b);
    const uint32_t qka  = smem_u32(qk);
    const int tid  = threadIdx.x;
    const int w    = tid >> 5;
    const int lane = tid & 31;
    const int grp  = lane >> 2;
    const int tig  = lane & 3;
    const int li   = lane & 7;
    const int sel  = lane >> 3;
    const int b    = blockIdx.x;
    const int mi   = w >> 1;
    const int nh   = w & 1;
    const int gt   = ((tid >> 6) << 5) | (tid & 31);   // group-local thread id

    // stage X as fp16
    const float4* xg = (const float4*)(x + (size_t)b * 16384);
    #pragma unroll
    for (int i = 0; i < 16; i++) {
        int idx = tid + 256 * i;
        int t = idx >> 6, c4 = idx & 63;
        float4 v = xg[idx];
        __half2* d = (__half2*)(xs + t * XP + c4 * 4);
        d[0] = __floats2half2_rn(v.x, v.y);
        d[1] = __floats2half2_rn(v.z, v.w);
    }
    // stage mask to smem (pitch 72, conflict-free float2)
    {
        const float2* mg = (const float2*)(mask + (size_t)(b & 4095) * 4096);
        #pragma unroll
        for (int i = 0; i < 8; i++) {
            int idx = tid + 256 * i;
            int r = idx >> 5, c2 = idx & 31;
            *(float2*)(mks + r * MKP + c2 * 2) = __ldg(mg + idx);
        }
    }

    // ldmatrix per-lane addresses
    const uint32_t addrA = qka + (((sel & 1) * 8 + li) * QKP + (sel >> 1) * 8) * 2;
    const uint32_t addrK = qka + (((sel >> 1) * 8 + li) * QKP + (sel & 1) * 8) * 2;
    const uint32_t addrV = qka + (((sel & 1) * 8 + li) * QKP + (sel >> 1) * 8) * 2;

    // prologue: head 0 chunk 0
    stage96g(wsa0, g_w1, gt, nh);
    CP_COMMIT();

    for (int h = 0; h < 8; h++) {
        const __half* w1h = g_w1 + h * 24576;
        // ---- GEMM1: QKV_h[64,96] = X @ W1_h^T ; group-local staging/barriers ----
        FragC acc[3];
        #pragma unroll
        for (int j = 0; j < 3; j++) wmma::fill_fragment(acc[j], 0.f);

        for (int kc = 0; kc < 8; kc++) {
            CP_WAIT0();
            if (kc == 0) __syncthreads(); else barg(1 + nh);
            if (kc < 7) {
                stage96g((kc & 1) ? wsa0 : wsa1, w1h + (kc + 1) * 32, gt, nh);
                CP_COMMIT();
            } else if (h < 7) {
                stage96g(wsa0, g_w1 + (h + 1) * 24576, gt, nh);   // next head chunk0
                CP_COMMIT();
            }
            __half* wb = (kc & 1) ? ws1 : ws0;
            #pragma unroll
            for (int k8 = 0; k8 < 2; k8++) {
                FragA fa;
                wmma::load_matrix_sync(fa, xs + mi * 16 * XP + kc * 32 + k8 * 16, XP);
                #pragma unroll
                for (int j = 0; j < 3; j++) {
                    FragBc fb;
                    wmma::load_matrix_sync(fb, wb + (nh * 3 + j) * 16 * WSP + k8 * 16, WSP);
                    wmma::mma_sync(acc[j], fa, fb, acc[j]);
                }
            }
        }

        // ---- register-direct fixup: acc (+bias) -> qk half2 ----
        #pragma unroll
        for (int j = 0; j < 3; j++) {
            int colb = (nh * 3 + j) * 16;
            #pragma unroll
            for (int p = 0; p < 4; p++) {
                int row = mi * 16 + grp + 8 * (p & 1);
                int col = colb + 8 * (p >> 1) + 2 * tig;
                float b0 = g_b1v[h * 96 + col];
                float b1 = g_b1v[h * 96 + col + 1];
                *(uint32_t*)(qk + row * QKP + col) =
                    packh2(acc[j].x[2 * p] + b0, acc[j].x[2 * p + 1] + b1);
            }
        }
        __syncthreads();

        // at last head: xs is dead -> prefetch GEMM4 chunk0 into ws4A (hides under attn h7)
        if (h == 7) {
            stage256g(w4aa, g_w4, gt, nh);
            CP_COMMIT();
        }

        // ======== register-resident attention ========
        float sD[8][4];
        #pragma unroll
        for (int c = 0; c < 8; c++)
            #pragma unroll
            for (int r = 0; r < 4; r++) sD[c][r] = 0.f;
        {
            uint32_t qa0[4], qa1[4];
            ldsm4(addrA + (mi * 16 * QKP) * 2,      qa0[0], qa0[1], qa0[2], qa0[3]);
            ldsm4(addrA + (mi * 16 * QKP + 16) * 2, qa1[0], qa1[1], qa1[2], qa1[3]);
            #pragma unroll
            for (int tg = 0; tg < 4; tg++) {
                uint32_t k0[4], k1[4];
                ldsm4(addrK + (tg * 16 * QKP + 32) * 2, k0[0], k0[1], k0[2], k0[3]);
                ldsm4(addrK + (tg * 16 * QKP + 48) * 2, k1[0], k1[1], k1[2], k1[3]);
                mma16816(sD[2 * tg + 0], qa0, k0[0], k0[1]);
                mma16816(sD[2 * tg + 0], qa1, k1[0], k1[1]);
                mma16816(sD[2 * tg + 1], qa0, k0[2], k0[3]);
                mma16816(sD[2 * tg + 1], qa1, k1[2], k1[3]);
            }
        }
        {
            int r0 = mi * 16 + grp, r1 = r0 + 8;
            const float* bfh = g_bf + h * 4096;
            float mx0 = -1e30f, mx1 = -1e30f;
            #pragma unroll
            for (int c = 0; c < 8; c++) {
                int col = 8 * c + 2 * tig;
                float2 f0 = __ldg((const float2*)(bfh + r0 * 64 + col));
                float2 f1 = __ldg((const float2*)(bfh + r1 * 64 + col));
                float2 m0 = *(const float2*)(mks + r0 * MKP + col);
                float2 m1 = *(const float2*)(mks + r1 * MKP + col);
                sD[c][0] += f0.x + m0.x;  sD[c][1] += f0.y + m0.y;
                sD[c][2] += f1.x + m1.x;  sD[c][3] += f1.y + m1.y;
                mx0 = fmaxf(mx0, fmaxf(sD[c][0], sD[c][1]));
                mx1 = fmaxf(mx1, fmaxf(sD[c][2], sD[c][3]));
            }
            mx0 = fmaxf(mx0, __shfl_xor_sync(0xffffffffu, mx0, 1));
            mx0 = fmaxf(mx0, __shfl_xor_sync(0xffffffffu, mx0, 2));
            mx1 = fmaxf(mx1, __shfl_xor_sync(0xffffffffu, mx1, 1));
            mx1 = fmaxf(mx1, __shfl_xor_sync(0xffffffffu, mx1, 2));
            float s0 = 0.f, s1 = 0.f;
            #pragma unroll
            for (int c = 0; c < 8; c++) {
                sD[c][0] = __expf(sD[c][0] - mx0);  s0 += sD[c][0];
                sD[c][1] = __expf(sD[c][1] - mx0);  s0 += sD[c][1];
                sD[c][2] = __expf(sD[c][2] - mx1);  s1 += sD[c][2];
                sD[c][3] = __expf(sD[c][3] - mx1);  s1 += sD[c][3];
            }
            s0 += __shfl_xor_sync(0xffffffffu, s0, 1);
            s0 += __shfl_xor_sync(0xffffffffu, s0, 2);
            s1 += __shfl_xor_sync(0xffffffffu, s1, 1);
            s1 += __shfl_xor_sync(0xffffffffu, s1, 2);
            float i0 = 1.f / s0, i1 = 1.f / s1;
            #pragma unroll
            for (int c = 0; c < 8; c++) {
                sD[c][0] *= i0;  sD[c][1] *= i0;
                sD[c][2] *= i1;  sD[c][3] *= i1;
            }
        }
        {
            float oD[2][4];
            #pragma unroll
            for (int ch = 0; ch < 2; ch++)
                #pragma unroll
                for (int r = 0; r < 4; r++) oD[ch][r] = 0.f;
            #pragma unroll
            for (int kf = 0; kf < 4; kf++) {
                uint32_t pa[4];
                pa[0] = packh2(sD[2 * kf][0],     sD[2 * kf][1]);
                pa[1] = packh2(sD[2 * kf][2],     sD[2 * kf][3]);
                pa[2] = packh2(sD[2 * kf + 1][0], sD[2 * kf + 1][1]);
                pa[3] = packh2(sD[2 * kf + 1][2], sD[2 * kf + 1][3]);
                uint32_t v[4];
                ldsm4t(addrV + (kf * 16 * QKP + 64 + nh * 16) * 2, v[0], v[1], v[2], v[3]);
                mma16816(oD[0], pa, v[0], v[1]);
                mma16816(oD[1], pa, v[2], v[3]);
            }
            #pragma unroll
            for (int ch = 0; ch < 2; ch++) {
                int col = h * 32 + nh * 16 + 8 * ch + 2 * tig;
                int r0 = mi * 16 + grp;
                *(uint32_t*)(ob + r0 * OBP + col)       = packh2(oD[ch][0], oD[ch][1]);
                *(uint32_t*)(ob + (r0 + 8) * OBP + col) = packh2(oD[ch][2], oD[ch][3]);
            }
        }
    }

    // ---------- GEMM4: out = Ob @ wp^T, single K loop over all 4 oc ----------
    FragC a4[4][2];
    #pragma unroll
    for (int oc = 0; oc < 4; oc++)
        #pragma unroll
        for (int j = 0; j < 2; j++) wmma::fill_fragment(a4[oc][j], 0.f);

    for (int kc = 0; kc < 8; kc++) {
        CP_WAIT0();
        if (kc == 0) __syncthreads(); else barg(1 + nh);   // kc0 CTA: ob visible, qk dead
        if (kc < 7) {
            stage256g((kc & 1) ? w4aa : w4ba, g_w4 + (kc + 1) * 32, gt, nh);
            CP_COMMIT();
        }
        __half* wb4 = (kc & 1) ? w4b : w4a;
        #pragma unroll
        for (int k8 = 0; k8 < 2; k8++) {
            FragA fa;
            wmma::load_matrix_sync(fa, ob + mi * 16 * OBP + kc * 32 + k8 * 16, OBP);
            #pragma unroll
            for (int oc = 0; oc < 4; oc++)
                #pragma unroll
                for (int j = 0; j < 2; j++) {
                    FragBc fb;
                    wmma::load_matrix_sync(fb, wb4 + (oc * 64 + nh * 32 + j * 16) * WSP + k8 * 16, WSP);
                    wmma::mma_sync(a4[oc][j], fa, fb, a4[oc][j]);
                }
        }
    }
    // register-direct epilogue: +bp, float2 global stores
    {
        float* orow = out + (size_t)b * 16384;
        #pragma unroll
        for (int oc = 0; oc < 4; oc++)
            #pragma unroll
            for (int j = 0; j < 2; j++) {
                int colb = oc * 64 + nh * 32 + j * 16;
                #pragma unroll
                for (int p = 0; p < 4; p++) {
                    int row = mi * 16 + grp + 8 * (p & 1);
                    int col = colb + 8 * (p >> 1) + 2 * tig;
                    float2 v;
                    v.x = a4[oc][j].x[2 * p]     + __ldg(bp + col);
                    v.y = a4[oc][j].x[2 * p + 1] + __ldg(bp + col + 1);
                    *(float2*)(orow + row * 256 + col) = v;
                }
            }
    }
}

extern "C" void kernel_launch(void* const* d_in, const int* in_sizes, int n_in,
                              void* d_out, int out_size)
{
    const float* x    = (const float*)d_in[0];
    const float* mask = (const float*)d_in[1];
    const float* wq   = (const float*)d_in[2];
    const float* bq   = (const float*)d_in[3];
    const float* wkv  = (const float*)d_in[4];
    const float* bkv  = (const float*)d_in[5];
    const float* wp   = (const float*)d_in[6];
    const float* bp   = (const float*)d_in[7];
    const float* bt   = (const float*)d_in[8];
    const int*   ri   = (const int*)d_in[9];
    float* out = (float*)d_out;

    prep_kernel<<<1155, 256>>>(wq, bq, wkv, bkv, wp, bt, ri);
    cudaFuncSetAttribute(winattn_h16f,
                         cudaFuncAttributeMaxDynamicSharedMemorySize, SMEM_BYTES);
    winattn_h16f<<<8192, 256, SMEM_BYTES>>>(x, mask, bp, out);
}